// round 10
// baseline (speedup 1.0000x reference)
#include <cuda_runtime.h>
#include <cuda_fp16.h>

#define NMAX 500000
#define GMAX 5000
#define HID 64
#define H1  128

// Scratch (static __device__ per allocation rules)
__device__ float4   d_agg[NMAX];         // (1+eps)*x + sum_{j->i} x_j
__device__ float    d_sums[GMAX * HID];  // per-graph h2 sums
__device__ float    d_cnt[GMAX];         // per-graph node counts (as float)
__device__ unsigned d_W1h[32 * 16];      // layer1 f16 B-frags (W1+bias), per-lane order
__device__ unsigned d_Bfrag[32 * 128];   // W2 as f16x2 m16n8k16 B-fragments, per-lane order
__device__ float    d_C2[HID];           // folded bias2

__device__ __forceinline__ void red4(float4* p, float4 v) {
    asm volatile("red.global.add.v4.f32 [%0], {%1, %2, %3, %4};"
                 :: "l"(p), "f"(v.x), "f"(v.y), "f"(v.z), "f"(v.w)
                 : "memory");
}

__device__ __forceinline__ void redf(float* p, float v) {
    asm volatile("red.global.add.f32 [%0], %1;" :: "l"(p), "f"(v) : "memory");
}

// m16n8k8 f16: A=2 regs, B=1 reg, C=f32
__device__ __forceinline__ void mma_f16_k8(float* c, unsigned a0, unsigned a1, unsigned b0) {
    asm volatile(
        "mma.sync.aligned.m16n8k8.row.col.f32.f16.f16.f32 "
        "{%0,%1,%2,%3},{%4,%5},{%6},{%0,%1,%2,%3};"
        : "+f"(c[0]), "+f"(c[1]), "+f"(c[2]), "+f"(c[3])
        : "r"(a0), "r"(a1), "r"(b0));
}

// m16n8k16 f16: A=4 regs, B=2 regs, C=f32
__device__ __forceinline__ void mma_f16(float* c, unsigned a0, unsigned a1,
                                        unsigned a2, unsigned a3,
                                        unsigned b0, unsigned b1) {
    asm volatile(
        "mma.sync.aligned.m16n8k16.row.col.f32.f16.f16.f32 "
        "{%0,%1,%2,%3},{%4,%5,%6,%7},{%8,%9},{%0,%1,%2,%3};"
        : "+f"(c[0]), "+f"(c[1]), "+f"(c[2]), "+f"(c[3])
        : "r"(a0), "r"(a1), "r"(a2), "r"(a3), "r"(b0), "r"(b1));
}

__device__ __forceinline__ unsigned pack_h2(float lo, float hi) {
    __half2 v = __floats2half2_rn(lo, hi);
    return *reinterpret_cast<unsigned*>(&v);
}

// pack two f32 into half2 with relu
__device__ __forceinline__ unsigned pack_relu_h2(float lo, float hi) {
    __half2 v = __floats2half2_rn(lo, hi);
    __half2 z = __half2half2(__ushort_as_half((unsigned short)0));
    v = __hmax2(v, z);
    return *reinterpret_cast<unsigned*>(&v);
}

// ---------------------------------------------------------------------------
// Merged prep + init. agg[i]=(1+eps)*x[i]; zero sums/counts; fold BN.
// Layer1 f16 B-frags (m16n8k8, B = 1 reg half2(k=2kc, 2kc+1; col)):
//   lane l (kc=l&3, grp=l>>2), s=0..15, col=8s+grp; K rows = [w1_0..w1_3, C1, 0,0,0]
// Layer2 f16 B-frags (m16n8k16), identity K-map: q = u*16 + nt*2 + j:
//   value = half2( W2f[16u+8j+2kc][o], W2f[16u+8j+2kc+1][o] ), o = 8nt+grp
// ---------------------------------------------------------------------------
__global__ void prep_init_kernel(const float4* __restrict__ x, const float* __restrict__ epsp,
                            const float* __restrict__ w1, const float* __restrict__ b1,
                            const float* __restrict__ g1, const float* __restrict__ be1,
                            const float* __restrict__ m1, const float* __restrict__ v1,
                            const float* __restrict__ w2, const float* __restrict__ b2,
                            const float* __restrict__ g2, const float* __restrict__ be2,
                            const float* __restrict__ m2, const float* __restrict__ v2,
                            int n, int G) {
    int idx = blockIdx.x * blockDim.x + threadIdx.x;
    if (idx < n) {
        float c = 1.f + *epsp;
        float4 v = x[idx];
        v.x *= c; v.y *= c; v.z *= c; v.w *= c;
        d_agg[idx] = v;
    }
    if (idx < G * HID) d_sums[idx] = 0.f;
    if (idx < G) d_cnt[idx] = 0.f;
    if (idx < 32 * 128) {
        int l = idx >> 7, q = idx & 127;
        int kc = l & 3, grp = l >> 2;
        int u = q >> 4, r = q & 15, nt = r >> 1, j = r & 1;
        int k0 = 16 * u + 8 * j + 2 * kc;
        int o = 8 * nt + grp;
        float s2 = g2[o] * rsqrtf(v2[o] + 1e-5f);
        d_Bfrag[idx] = pack_h2(w2[k0 * HID + o] * s2, w2[(k0 + 1) * HID + o] * s2);
    }
    if (idx < 32 * 16) {
        int l = idx >> 4, s = idx & 15;
        int kc = l & 3, grp = l >> 2;
        int col = 8 * s + grp;
        float s1 = g1[col] * rsqrtf(v1[col] + 1e-5f);
        float lo, hi;
        if (kc == 0)      { lo = w1[0 * H1 + col] * s1; hi = w1[1 * H1 + col] * s1; }
        else if (kc == 1) { lo = w1[2 * H1 + col] * s1; hi = w1[3 * H1 + col] * s1; }
        else if (kc == 2) { lo = (b1[col] - m1[col]) * s1 + be1[col]; hi = 0.f; }
        else              { lo = 0.f; hi = 0.f; }
        d_W1h[idx] = pack_h2(lo, hi);
    }
    if (idx < HID) {
        float s2 = g2[idx] * rsqrtf(v2[idx] + 1e-5f);
        d_C2[idx] = (b2[idx] - m2[idx]) * s2 + be2[idx];
    }
}

// Empty spacer kernels: shift edge_kernel into the profiler's capture slot (#4).
__global__ void dummy_kernel() {}

// ---------------------------------------------------------------------------
// Edge scatter: agg[dst] += x[src], one vectorized RED per edge, 8 edges/thread.
// ---------------------------------------------------------------------------
__global__ void edge_kernel(const int* __restrict__ ei, const float4* __restrict__ x, int E) {
    int t = blockIdx.x * blockDim.x + threadIdx.x;
    int e = t * 8;
    if (e + 7 < E) {
        int4 s0 = __ldcs((const int4*)(ei + e));
        int4 s1 = __ldcs((const int4*)(ei + e + 4));
        int4 d0 = __ldcs((const int4*)(ei + E + e));
        int4 d1 = __ldcs((const int4*)(ei + E + e + 4));
        float4 v0 = __ldg(x + s0.x);
        float4 v1 = __ldg(x + s0.y);
        float4 v2 = __ldg(x + s0.z);
        float4 v3 = __ldg(x + s0.w);
        float4 v4 = __ldg(x + s1.x);
        float4 v5 = __ldg(x + s1.y);
        float4 v6 = __ldg(x + s1.z);
        float4 v7 = __ldg(x + s1.w);
        red4(&d_agg[d0.x], v0);
        red4(&d_agg[d0.y], v1);
        red4(&d_agg[d0.z], v2);
        red4(&d_agg[d0.w], v3);
        red4(&d_agg[d1.x], v4);
        red4(&d_agg[d1.y], v5);
        red4(&d_agg[d1.z], v6);
        red4(&d_agg[d1.w], v7);
    } else if (e < E) {
        for (int q = e; q < E; q++) {
            int s = ei[q], d = ei[E + q];
            red4(&d_agg[d], __ldg(x + s));
        }
    }
}

// ---------------------------------------------------------------------------
// Persistent fused MLP + pool, all-f16 tensor path.
// Layer1: f16 m16n8k8, A=[x,1,0,0,0] as half2 pairs (kc<2 lanes carry x,
// kc=2 carries the bias one-hot, kc=3 zeros). Layer1 acc pairs pack directly
// into f16 m16n8k16 layer2 A-fragments (identity K-map).
// Pool: float4 segmented scan + red.v4 + counts.
// ---------------------------------------------------------------------------
#define SM_BF   (32 * 132)          // layer2 B fragments (uint32 half2), padded
#define SM_W1   (32 * 17)           // layer1 B fragments (uint32 half2), odd stride
#define SM_H2   (256 * 68)          // h2 staging, stride 68 (16B-aligned rows)
#define MLP_SMEM_F (SM_BF + SM_W1 + SM_H2 + 64 + 256)
#define MLP_SMEM (MLP_SMEM_F * 4)

__global__ void __launch_bounds__(256, 2)
mlp_kernel(const int* __restrict__ batch, int n, int numTiles) {
    extern __shared__ float sm[];
    unsigned* Bf  = (unsigned*)sm;           // [32][132]
    unsigned* W1s = (unsigned*)(sm + SM_BF); // [32][17]
    float*  h2s  = sm + SM_BF + SM_W1;       // [256][68]
    float*  C2s  = sm + SM_BF + SM_W1 + SM_H2;
    int*    batchs = (int*)(C2s + 64);

    int tid = threadIdx.x;
    int lane = tid & 31, warp = tid >> 5;
    int grp = lane >> 2;      // lane / 4
    int kc  = lane & 3;       // lane % 4

    for (int i = tid; i < 32 * 128; i += 256) {
        int l = i >> 7, q = i & 127;
        Bf[l * 132 + q] = d_Bfrag[i];
    }
    for (int i = tid; i < 32 * 16; i += 256) {
        int l = i >> 4, q = i & 15;
        W1s[l * 17 + q] = d_W1h[i];
    }
    if (tid < HID) C2s[tid] = d_C2[tid];

    const uint4*    bptr  = (const uint4*)(Bf + lane * 132);
    const unsigned* w1p   = W1s + lane * 17;
    const float2*   xs2   = (const float2*)d_agg;   // row r = xs2[2r], xs2[2r+1]
    unsigned Aconst = (kc == 2) ? 0x00003C00u : 0u; // half2(1,0) for bias K-pair

    // prologue prefetch for first tile (kc<2 lanes carry x data)
    float2 pv2[4];
    int    pb;
    {
        int tile0 = blockIdx.x;
        int rb = tile0 * 256 + warp * 32 + grp;
        if (kc < 2) {
            #pragma unroll
            for (int t = 0; t < 4; t++) pv2[t] = xs2[min(rb + 8 * t, n - 1) * 2 + kc];
        }
        int nd = tile0 * 256 + tid;
        pb = (nd < n) ? batch[nd] : -1;
    }

    for (int tile = blockIdx.x; tile < numTiles; tile += gridDim.x) {
        __syncthreads();   // weights ready (first iter) / prior scan done

        batchs[tid] = pb;

        unsigned a0[2], a1[2];
        if (kc < 2) {
            a0[0] = pack_h2(pv2[0].x, pv2[0].y); a1[0] = pack_h2(pv2[1].x, pv2[1].y);
            a0[1] = pack_h2(pv2[2].x, pv2[2].y); a1[1] = pack_h2(pv2[3].x, pv2[3].y);
        } else {
            a0[0] = a0[1] = a1[0] = a1[1] = Aconst;
        }

        // issue prefetch for the NEXT tile now; consumed after this tile's work
        {
            int tile2 = tile + gridDim.x;
            int tc = min(tile2, numTiles - 1);
            int rb = tc * 256 + warp * 32 + grp;
            if (kc < 2) {
                #pragma unroll
                for (int t = 0; t < 4; t++) pv2[t] = xs2[min(rb + 8 * t, n - 1) * 2 + kc];
            }
            int nd = tile2 * 256 + tid;
            pb = (tile2 < numTiles && nd < n) ? batch[min(nd, n - 1)] : -1;
        }

        float acc[2][8][4];
        #pragma unroll
        for (int t = 0; t < 2; t++)
            #pragma unroll
            for (int nt = 0; nt < 8; nt++)
                #pragma unroll
                for (int i = 0; i < 4; i++) acc[t][nt][i] = 0.f;

        #pragma unroll
        for (int u = 0; u < 8; u++) {
            // A fragments for K-window [16u, 16u+16): Af[slot][Mtile]
            unsigned Af[4][2];
            #pragma unroll
            for (int h = 0; h < 2; h++) {       // s = 2u + h (8 h1 cols each)
                unsigned bw = w1p[2 * u + h];
                #pragma unroll
                for (int t = 0; t < 2; t++) {
                    float d1[4] = {0.f, 0.f, 0.f, 0.f};
                    mma_f16_k8(d1, a0[t], a1[t], bw);
                    // c0,c1 = (row grp, cols 2kc,2kc+1); c2,c3 = (row grp+8)
                    Af[2 * h][t]     = pack_relu_h2(d1[0], d1[1]);  // a0 / a2
                    Af[2 * h + 1][t] = pack_relu_h2(d1[2], d1[3]);  // a1 / a3
                }
            }
            // layer2: f16 k16 mma, 8 n-tiles
            #pragma unroll
            for (int np = 0; np < 4; np++) {
                uint4 bv = bptr[u * 4 + np];
                #pragma unroll
                for (int t = 0; t < 2; t++) {
                    mma_f16(acc[t][2 * np],     Af[0][t], Af[1][t], Af[2][t], Af[3][t], bv.x, bv.y);
                    mma_f16(acc[t][2 * np + 1], Af[0][t], Af[1][t], Af[2][t], Af[3][t], bv.z, bv.w);
                }
            }
        }

        // epilogue: bias + relu, float2 stores into h2 staging
        int r0l = warp * 32 + grp;
        #pragma unroll
        for (int t = 0; t < 2; t++) {
            int rl = r0l + 16 * t;
            #pragma unroll
            for (int nt = 0; nt < 8; nt++) {
                int c = nt * 8 + 2 * kc;
                float2 lo = make_float2(fmaxf(acc[t][nt][0] + C2s[c], 0.f),
                                        fmaxf(acc[t][nt][1] + C2s[c + 1], 0.f));
                float2 hi = make_float2(fmaxf(acc[t][nt][2] + C2s[c], 0.f),
                                        fmaxf(acc[t][nt][3] + C2s[c + 1], 0.f));
                *(float2*)&h2s[rl * 68 + c]       = lo;
                *(float2*)&h2s[(rl + 8) * 68 + c] = hi;
            }
        }
        __syncthreads();

        // segmented pooling scan: thread = (4-col group, 16-row part).
        // Col-leader threads also accumulate per-graph node counts.
        int col4 = (tid & 15) * 4;
        int part = tid >> 4;            // 0..15
        bool leader = (tid & 15) == 0;
        float4 run = make_float4(0.f, 0.f, 0.f, 0.f);
        float cnt = 0.f;
        int curg = -1;
        #pragma unroll
        for (int i = 0; i < 16; i++) {
            int ln = part * 16 + i;
            int g = batchs[ln];
            if (g != curg) {
                if (curg >= 0) {
                    red4((float4*)&d_sums[curg * HID + col4], run);
                    if (leader) redf(&d_cnt[curg], cnt);
                }
                if (g < 0) { curg = -1; break; }
                run = make_float4(0.f, 0.f, 0.f, 0.f);
                cnt = 0.f;
                curg = g;
            }
            float4 v = *(const float4*)&h2s[ln * 68 + col4];
            run.x += v.x; run.y += v.y; run.z += v.z; run.w += v.w;
            cnt += 1.f;
        }
        if (curg >= 0) {
            red4((float4*)&d_sums[curg * HID + col4], run);
            if (leader) redf(&d_cnt[curg], cnt);
        }
    }
}

// ---------------------------------------------------------------------------
// Final: warp-per-graph. Each lane handles 2 of the 64 hidden channels
// (coalesced), butterfly-reduces the two logits, lane 0 writes log_softmax.
// ---------------------------------------------------------------------------
__global__ void final_kernel(const float* __restrict__ w3, const float* __restrict__ b3,
                             float* __restrict__ out, int G) {
    int gw = (blockIdx.x * blockDim.x + threadIdx.x) >> 5;
    int lane = threadIdx.x & 31;
    if (gw >= G) return;

    float inv = 1.f / fmaxf(d_cnt[gw], 1.f);
    const float* sp = &d_sums[gw * HID];
    float a = sp[lane]      * inv;
    float b = sp[lane + 32] * inv;
    float w0a = __ldg(&w3[2 * lane]);
    float w1a = __ldg(&w3[2 * lane + 1]);
    float w0b = __ldg(&w3[2 * (lane + 32)]);
    float w1b = __ldg(&w3[2 * (lane + 32) + 1]);
    float l0 = fmaf(a, w0a, b * w0b);
    float l1 = fmaf(a, w1a, b * w1b);
    #pragma unroll
    for (int off = 16; off; off >>= 1) {
        l0 += __shfl_xor_sync(0xFFFFFFFFu, l0, off);
        l1 += __shfl_xor_sync(0xFFFFFFFFu, l1, off);
    }
    if (lane == 0) {
        l0 += __ldg(&b3[0]);
        l1 += __ldg(&b3[1]);
        float m = fmaxf(l0, l1);
        float lse = m + logf(expf(l0 - m) + expf(l1 - m));
        *(float2*)&out[2 * gw] = make_float2(l0 - lse, l1 - lse);
    }
}

// ---------------------------------------------------------------------------
extern "C" void kernel_launch(void* const* d_in, const int* in_sizes, int n_in,
                              void* d_out, int out_size) {
    const float* x   = (const float*)d_in[0];
    const float* eps = (const float*)d_in[1];
    const float* w1  = (const float*)d_in[2];
    const float* b1  = (const float*)d_in[3];
    const float* g1  = (const float*)d_in[4];
    const float* be1 = (const float*)d_in[5];
    const float* m1  = (const float*)d_in[6];
    const float* v1  = (const float*)d_in[7];
    const float* w2  = (const float*)d_in[8];
    const float* b2  = (const float*)d_in[9];
    const float* g2  = (const float*)d_in[10];
    const float* be2 = (const float*)d_in[11];
    const float* m2  = (const float*)d_in[12];
    const float* v2  = (const float*)d_in[13];
    const float* w3  = (const float*)d_in[14];
    const float* b3  = (const float*)d_in[15];
    const int*   ei  = (const int*)d_in[16];
    const int*   batch = (const int*)d_in[17];

    int n = in_sizes[0] / 4;
    int E = in_sizes[16] / 2;
    int G = out_size / 2;

    static int smem_set = 0;
    if (!smem_set) {
        cudaFuncSetAttribute(mlp_kernel, cudaFuncAttributeMaxDynamicSharedMemorySize, MLP_SMEM);
        smem_set = 1;
    }

    int piCover = n;
    if (G * HID > piCover) piCover = G * HID;
    if (32 * 256 > piCover) piCover = 32 * 256;
    prep_init_kernel<<<(piCover + 255) / 256, 256>>>((const float4*)x, eps,
                                                w1, b1, g1, be1, m1, v1,
                                                w2, b2, g2, be2, m2, v2, n, G);
    // spacers: put edge_kernel into the profiler's deterministic 4th-launch slot
    dummy_kernel<<<1, 32>>>();
    dummy_kernel<<<1, 32>>>();
    int et = (E + 7) / 8;
    edge_kernel<<<(et + 255) / 256, 256>>>(ei, (const float4*)x, E);
    int numTiles = (n + 255) / 256;
    int mlpGrid = 296;                      // 2 CTAs x 148 SMs
    if (mlpGrid > numTiles) mlpGrid = numTiles;
    mlp_kernel<<<mlpGrid, 256, MLP_SMEM>>>(batch, n, numTiles);
    final_kernel<<<(G * 32 + 255) / 256, 256>>>(w3, b3, (float*)d_out, G);
}

// round 11
// speedup vs baseline: 1.0536x; 1.0536x over previous
#include <cuda_runtime.h>
#include <cuda_fp16.h>

#define NMAX 500000
#define GMAX 5000
#define HID 64
#define H1  128

// Scratch (static __device__ per allocation rules)
__device__ float4   d_agg[NMAX];         // (1+eps)*x + sum_{j->i} x_j
__device__ float    d_sums[GMAX * HID];  // per-graph h2 sums
__device__ float    d_cnt[GMAX];         // per-graph node counts (as float)
__device__ float    d_W1f[32 * 32];      // layer1 tf32 B-frags (W1+bias row), per-lane order
__device__ unsigned d_Bfrag[32 * 128];   // W2 as f16x2 m16n8k16 B-fragments, per-lane order
__device__ float    d_C2[HID];           // folded bias2

__device__ __forceinline__ unsigned f2tf(float f) {
    unsigned r;
    asm("cvt.rna.tf32.f32 %0, %1;" : "=r"(r) : "f"(f));
    return r;
}

__device__ __forceinline__ void red4(float4* p, float4 v) {
    asm volatile("red.global.add.v4.f32 [%0], {%1, %2, %3, %4};"
                 :: "l"(p), "f"(v.x), "f"(v.y), "f"(v.z), "f"(v.w)
                 : "memory");
}

__device__ __forceinline__ void redf(float* p, float v) {
    asm volatile("red.global.add.f32 [%0], %1;" :: "l"(p), "f"(v) : "memory");
}

__device__ __forceinline__ void mma_tf32(float* c, unsigned a0, unsigned a1,
                                         unsigned a2, unsigned a3,
                                         unsigned b0, unsigned b1) {
    asm volatile(
        "mma.sync.aligned.m16n8k8.row.col.f32.tf32.tf32.f32 "
        "{%0,%1,%2,%3},{%4,%5,%6,%7},{%8,%9},{%0,%1,%2,%3};"
        : "+f"(c[0]), "+f"(c[1]), "+f"(c[2]), "+f"(c[3])
        : "r"(a0), "r"(a1), "r"(a2), "r"(a3), "r"(b0), "r"(b1));
}

// m16n8k16 f16: A=4 regs, B=2 regs, C=f32
__device__ __forceinline__ void mma_f16(float* c, unsigned a0, unsigned a1,
                                        unsigned a2, unsigned a3,
                                        unsigned b0, unsigned b1) {
    asm volatile(
        "mma.sync.aligned.m16n8k16.row.col.f32.f16.f16.f32 "
        "{%0,%1,%2,%3},{%4,%5,%6,%7},{%8,%9},{%0,%1,%2,%3};"
        : "+f"(c[0]), "+f"(c[1]), "+f"(c[2]), "+f"(c[3])
        : "r"(a0), "r"(a1), "r"(a2), "r"(a3), "r"(b0), "r"(b1));
}

__device__ __forceinline__ unsigned pack_h2(float lo, float hi) {
    __half2 v = __floats2half2_rn(lo, hi);
    return *reinterpret_cast<unsigned*>(&v);
}

// pack two f32 into half2 with relu
__device__ __forceinline__ unsigned pack_relu_h2(float lo, float hi) {
    __half2 v = __floats2half2_rn(lo, hi);
    __half2 z = __half2half2(__ushort_as_half((unsigned short)0));
    v = __hmax2(v, z);
    return *reinterpret_cast<unsigned*>(&v);
}

// ---------------------------------------------------------------------------
// Merged prep + init. agg[i]=(1+eps)*x[i]; zero sums/counts; fold BN.
// Layer1 B-frags (tf32 m16n8k8): lane l (kc=l&3, grp=l>>2), q = 2*nt + j:
//   j=0 -> W1fold[k=kc][col=8nt+grp]      j=1 -> kc==0 ? C1fold[col] : 0
// Layer2 f16 B-frags (m16n8k16), identity K-map: q = u*16 + nt*2 + j:
//   value = half2( W2f[16u+8j+2kc][o], W2f[16u+8j+2kc+1][o] ), o = 8nt+grp
// ---------------------------------------------------------------------------
__global__ void prep_init_kernel(const float4* __restrict__ x, const float* __restrict__ epsp,
                            const float* __restrict__ w1, const float* __restrict__ b1,
                            const float* __restrict__ g1, const float* __restrict__ be1,
                            const float* __restrict__ m1, const float* __restrict__ v1,
                            const float* __restrict__ w2, const float* __restrict__ b2,
                            const float* __restrict__ g2, const float* __restrict__ be2,
                            const float* __restrict__ m2, const float* __restrict__ v2,
                            int n, int G) {
    int idx = blockIdx.x * blockDim.x + threadIdx.x;
    if (idx < n) {
        float c = 1.f + *epsp;
        float4 v = x[idx];
        v.x *= c; v.y *= c; v.z *= c; v.w *= c;
        d_agg[idx] = v;
    }
    if (idx < G * HID) d_sums[idx] = 0.f;
    if (idx < G) d_cnt[idx] = 0.f;
    if (idx < 32 * 128) {
        int l = idx >> 7, q = idx & 127;
        int kc = l & 3, grp = l >> 2;
        int u = q >> 4, r = q & 15, nt = r >> 1, j = r & 1;
        int k0 = 16 * u + 8 * j + 2 * kc;
        int o = 8 * nt + grp;
        float s2 = g2[o] * rsqrtf(v2[o] + 1e-5f);
        d_Bfrag[idx] = pack_h2(w2[k0 * HID + o] * s2, w2[(k0 + 1) * HID + o] * s2);
    }
    if (idx < 32 * 32) {
        int l = idx >> 5, q = idx & 31;
        int kc = l & 3, grp = l >> 2;
        int nt = q >> 1, j = q & 1;
        int col = 8 * nt + grp;
        float s1 = g1[col] * rsqrtf(v1[col] + 1e-5f);
        float val;
        if (j == 0)       val = w1[kc * H1 + col] * s1;
        else if (kc == 0) val = (b1[col] - m1[col]) * s1 + be1[col];
        else              val = 0.f;
        d_W1f[idx] = __uint_as_float(f2tf(val));
    }
    if (idx < HID) {
        float s2 = g2[idx] * rsqrtf(v2[idx] + 1e-5f);
        d_C2[idx] = (b2[idx] - m2[idx]) * s2 + be2[idx];
    }
}

// ---------------------------------------------------------------------------
// Edge scatter: agg[dst] += x[src], one vectorized RED per edge, 8 edges/thread.
// Index stream: evict-first (.cs). Gathers: __ldcg — 97% L1-miss data, so skip
// the L1 line allocation/fill (L1tex measured 81% busy as a co-bottleneck).
// ---------------------------------------------------------------------------
__global__ void edge_kernel(const int* __restrict__ ei, const float4* __restrict__ x, int E) {
    int t = blockIdx.x * blockDim.x + threadIdx.x;
    int e = t * 8;
    if (e + 7 < E) {
        int4 s0 = __ldcs((const int4*)(ei + e));
        int4 s1 = __ldcs((const int4*)(ei + e + 4));
        int4 d0 = __ldcs((const int4*)(ei + E + e));
        int4 d1 = __ldcs((const int4*)(ei + E + e + 4));
        float4 v0 = __ldcg(x + s0.x);
        float4 v1 = __ldcg(x + s0.y);
        float4 v2 = __ldcg(x + s0.z);
        float4 v3 = __ldcg(x + s0.w);
        float4 v4 = __ldcg(x + s1.x);
        float4 v5 = __ldcg(x + s1.y);
        float4 v6 = __ldcg(x + s1.z);
        float4 v7 = __ldcg(x + s1.w);
        red4(&d_agg[d0.x], v0);
        red4(&d_agg[d0.y], v1);
        red4(&d_agg[d0.z], v2);
        red4(&d_agg[d0.w], v3);
        red4(&d_agg[d1.x], v4);
        red4(&d_agg[d1.y], v5);
        red4(&d_agg[d1.z], v6);
        red4(&d_agg[d1.w], v7);
    } else if (e < E) {
        for (int q = e; q < E; q++) {
            int s = ei[q], d = ei[E + q];
            red4(&d_agg[d], __ldcg(x + s));
        }
    }
}

// ---------------------------------------------------------------------------
// Persistent fused MLP + pool (R9-proven config). Layer1: tf32 m16n8k8
// (A=[x,1,0,0,0], bias via K row). Layer1 acc pairs pack directly into f16
// m16n8k16 layer2 A-fragments (identity K-map). Software-pipelined A/batch
// prefetch across tiles. Pool: float4 segmented scan + red.v4 + counts.
// ---------------------------------------------------------------------------
#define SM_BF   (32 * 132)          // layer2 B fragments (uint32 half2), padded
#define SM_W1   (32 * 34)           // layer1 B fragments
#define SM_H2   (256 * 68)          // h2 staging, stride 68 (16B-aligned rows)
#define MLP_SMEM_F (SM_BF + SM_W1 + SM_H2 + 64 + 256)
#define MLP_SMEM (MLP_SMEM_F * 4)

__global__ void __launch_bounds__(256, 2)
mlp_kernel(const int* __restrict__ batch, int n, int numTiles) {
    extern __shared__ float sm[];
    unsigned* Bf  = (unsigned*)sm;           // [32][132]
    float*  W1s  = sm + SM_BF;               // [32][34]
    float*  h2s  = sm + SM_BF + SM_W1;       // [256][68]
    float*  C2s  = sm + SM_BF + SM_W1 + SM_H2;
    int*    batchs = (int*)(C2s + 64);

    int tid = threadIdx.x;
    int lane = tid & 31, warp = tid >> 5;
    int grp = lane >> 2;      // lane / 4
    int kc  = lane & 3;       // lane % 4

    for (int i = tid; i < 32 * 128; i += 256) {
        int l = i >> 7, q = i & 127;
        Bf[l * 132 + q] = d_Bfrag[i];
    }
    for (int i = tid; i < 32 * 32; i += 256) {
        int l = i >> 5, q = i & 31;
        W1s[l * 34 + q] = d_W1f[i];
    }
    if (tid < HID) C2s[tid] = d_C2[tid];

    const uint4*  bptr  = (const uint4*)(Bf + lane * 132);
    const float2* w1ptr = (const float2*)(W1s + lane * 34);
    const float*  xs    = (const float*)d_agg;
    unsigned A2 = (kc == 0) ? 0x3F800000u : 0u;   // bias-row A value (tf32 1.0)

    // prologue prefetch for first tile
    float pv[4];
    int   pb;
    {
        int tile0 = blockIdx.x;
        int rb = tile0 * 256 + warp * 32 + grp;
        #pragma unroll
        for (int t = 0; t < 4; t++) pv[t] = xs[min(rb + 8 * t, n - 1) * 4 + kc];
        int nd = tile0 * 256 + tid;
        pb = (nd < n) ? batch[nd] : -1;
    }

    for (int tile = blockIdx.x; tile < numTiles; tile += gridDim.x) {
        __syncthreads();   // weights ready (first iter) / prior scan done

        batchs[tid] = pb;

        unsigned a0[2], a1[2];
        a0[0] = f2tf(pv[0]); a1[0] = f2tf(pv[1]);
        a0[1] = f2tf(pv[2]); a1[1] = f2tf(pv[3]);

        // issue prefetch for the NEXT tile now; consumed after this tile's work
        {
            int tile2 = tile + gridDim.x;
            int tc = min(tile2, numTiles - 1);
            int rb = tc * 256 + warp * 32 + grp;
            #pragma unroll
            for (int t = 0; t < 4; t++) pv[t] = xs[min(rb + 8 * t, n - 1) * 4 + kc];
            int nd = tile2 * 256 + tid;
            pb = (tile2 < numTiles && nd < n) ? batch[min(nd, n - 1)] : -1;
        }

        float acc[2][8][4];
        #pragma unroll
        for (int t = 0; t < 2; t++)
            #pragma unroll
            for (int nt = 0; nt < 8; nt++)
                #pragma unroll
                for (int i = 0; i < 4; i++) acc[t][nt][i] = 0.f;

        #pragma unroll
        for (int u = 0; u < 8; u++) {
            // A fragments for K-window [16u, 16u+16): Af[slot][Mtile]
            unsigned Af[4][2];
            #pragma unroll
            for (int h = 0; h < 2; h++) {       // s = 2u + h (8 h1 cols each)
                float2 bw = w1ptr[2 * u + h];
                unsigned bb0 = __float_as_uint(bw.x), bb1 = __float_as_uint(bw.y);
                #pragma unroll
                for (int t = 0; t < 2; t++) {
                    float d1[4] = {0.f, 0.f, 0.f, 0.f};
                    mma_tf32(d1, a0[t], a1[t], A2, A2, bb0, bb1);
                    // c0,c1 = (row grp, cols 2kc,2kc+1); c2,c3 = (row grp+8)
                    Af[2 * h][t]     = pack_relu_h2(d1[0], d1[1]);  // a0 / a2
                    Af[2 * h + 1][t] = pack_relu_h2(d1[2], d1[3]);  // a1 / a3
                }
            }
            // layer2: f16 k16 mma, 8 n-tiles
            #pragma unroll
            for (int np = 0; np < 4; np++) {
                uint4 bv = bptr[u * 4 + np];
                #pragma unroll
                for (int t = 0; t < 2; t++) {
                    mma_f16(acc[t][2 * np],     Af[0][t], Af[1][t], Af[2][t], Af[3][t], bv.x, bv.y);
                    mma_f16(acc[t][2 * np + 1], Af[0][t], Af[1][t], Af[2][t], Af[3][t], bv.z, bv.w);
                }
            }
        }

        // epilogue: bias + relu, float2 stores into h2 staging
        int r0l = warp * 32 + grp;
        #pragma unroll
        for (int t = 0; t < 2; t++) {
            int rl = r0l + 16 * t;
            #pragma unroll
            for (int nt = 0; nt < 8; nt++) {
                int c = nt * 8 + 2 * kc;
                float2 lo = make_float2(fmaxf(acc[t][nt][0] + C2s[c], 0.f),
                                        fmaxf(acc[t][nt][1] + C2s[c + 1], 0.f));
                float2 hi = make_float2(fmaxf(acc[t][nt][2] + C2s[c], 0.f),
                                        fmaxf(acc[t][nt][3] + C2s[c + 1], 0.f));
                *(float2*)&h2s[rl * 68 + c]       = lo;
                *(float2*)&h2s[(rl + 8) * 68 + c] = hi;
            }
        }
        __syncthreads();

        // segmented pooling scan: thread = (4-col group, 16-row part).
        // Col-leader threads also accumulate per-graph node counts.
        int col4 = (tid & 15) * 4;
        int part = tid >> 4;            // 0..15
        bool leader = (tid & 15) == 0;
        float4 run = make_float4(0.f, 0.f, 0.f, 0.f);
        float cnt = 0.f;
        int curg = -1;
        #pragma unroll
        for (int i = 0; i < 16; i++) {
            int ln = part * 16 + i;
            int g = batchs[ln];
            if (g != curg) {
                if (curg >= 0) {
                    red4((float4*)&d_sums[curg * HID + col4], run);
                    if (leader) redf(&d_cnt[curg], cnt);
                }
                if (g < 0) { curg = -1; break; }
                run = make_float4(0.f, 0.f, 0.f, 0.f);
                cnt = 0.f;
                curg = g;
            }
            float4 v = *(const float4*)&h2s[ln * 68 + col4];
            run.x += v.x; run.y += v.y; run.z += v.z; run.w += v.w;
            cnt += 1.f;
        }
        if (curg >= 0) {
            red4((float4*)&d_sums[curg * HID + col4], run);
            if (leader) redf(&d_cnt[curg], cnt);
        }
    }
}

// ---------------------------------------------------------------------------
// Final: warp-per-graph. Each lane handles 2 of the 64 hidden channels
// (coalesced), butterfly-reduces the two logits, lane 0 writes log_softmax.
// ---------------------------------------------------------------------------
__global__ void final_kernel(const float* __restrict__ w3, const float* __restrict__ b3,
                             float* __restrict__ out, int G) {
    int gw = (blockIdx.x * blockDim.x + threadIdx.x) >> 5;
    int lane = threadIdx.x & 31;
    if (gw >= G) return;

    float inv = 1.f / fmaxf(d_cnt[gw], 1.f);
    const float* sp = &d_sums[gw * HID];
    float a = sp[lane]      * inv;
    float b = sp[lane + 32] * inv;
    float w0a = __ldg(&w3[2 * lane]);
    float w1a = __ldg(&w3[2 * lane + 1]);
    float w0b = __ldg(&w3[2 * (lane + 32)]);
    float w1b = __ldg(&w3[2 * (lane + 32) + 1]);
    float l0 = fmaf(a, w0a, b * w0b);
    float l1 = fmaf(a, w1a, b * w1b);
    #pragma unroll
    for (int off = 16; off; off >>= 1) {
        l0 += __shfl_xor_sync(0xFFFFFFFFu, l0, off);
        l1 += __shfl_xor_sync(0xFFFFFFFFu, l1, off);
    }
    if (lane == 0) {
        l0 += __ldg(&b3[0]);
        l1 += __ldg(&b3[1]);
        float m = fmaxf(l0, l1);
        float lse = m + logf(expf(l0 - m) + expf(l1 - m));
        *(float2*)&out[2 * gw] = make_float2(l0 - lse, l1 - lse);
    }
}

// ---------------------------------------------------------------------------
extern "C" void kernel_launch(void* const* d_in, const int* in_sizes, int n_in,
                              void* d_out, int out_size) {
    const float* x   = (const float*)d_in[0];
    const float* eps = (const float*)d_in[1];
    const float* w1  = (const float*)d_in[2];
    const float* b1  = (const float*)d_in[3];
    const float* g1  = (const float*)d_in[4];
    const float* be1 = (const float*)d_in[5];
    const float* m1  = (const float*)d_in[6];
    const float* v1  = (const float*)d_in[7];
    const float* w2  = (const float*)d_in[8];
    const float* b2  = (const float*)d_in[9];
    const float* g2  = (const float*)d_in[10];
    const float* be2 = (const float*)d_in[11];
    const float* m2  = (const float*)d_in[12];
    const float* v2  = (const float*)d_in[13];
    const float* w3  = (const float*)d_in[14];
    const float* b3  = (const float*)d_in[15];
    const int*   ei  = (const int*)d_in[16];
    const int*   batch = (const int*)d_in[17];

    int n = in_sizes[0] / 4;
    int E = in_sizes[16] / 2;
    int G = out_size / 2;

    static int smem_set = 0;
    if (!smem_set) {
        cudaFuncSetAttribute(mlp_kernel, cudaFuncAttributeMaxDynamicSharedMemorySize, MLP_SMEM);
        smem_set = 1;
    }

    int piCover = n;
    if (G * HID > piCover) piCover = G * HID;
    if (32 * 256 > piCover) piCover = 32 * 256;
    prep_init_kernel<<<(piCover + 255) / 256, 256>>>((const float4*)x, eps,
                                                w1, b1, g1, be1, m1, v1,
                                                w2, b2, g2, be2, m2, v2, n, G);
    int et = (E + 7) / 8;
    edge_kernel<<<(et + 255) / 256, 256>>>(ei, (const float4*)x, E);
    int numTiles = (n + 255) / 256;
    int mlpGrid = 296;                      // 2 CTAs x 148 SMs
    if (mlpGrid > numTiles) mlpGrid = numTiles;
    mlp_kernel<<<mlpGrid, 256, MLP_SMEM>>>(batch, n, numTiles);
    final_kernel<<<(G * 32 + 255) / 256, 256>>>(w3, b3, (float*)d_out, G);
}